// round 11
// baseline (speedup 1.0000x reference)
#include <cuda_runtime.h>
#include <cuda_bf16.h>
#include <math.h>

// ---------------------------------------------------------------------------
// Problem constants
// ---------------------------------------------------------------------------
#define B_    2
#define Q_    16
#define BQ_   32
#define N0_   4096
#define N1_   1024
#define N2_   256
#define DIM_  296
#define CTX_  288
#define HEADS_ 8
#define I1_   144
#define I2_   72
#define I3_   36
#define EPS_  1e-5f

// ---------------------------------------------------------------------------
// Scratch (device globals)
// ---------------------------------------------------------------------------
__device__ float g_W1f[DIM_ * DIM_], g_b1f[DIM_];
__device__ float g_b2f[I1_], g_fb1f[I1_], g_fb2f[I2_], g_gb1f[I2_], g_gb2f[I3_];
__device__ float g_gW2f[I3_ * I2_];

// chunked k-major weights: [kc][m][k8]
__device__ float g_W2c[37 * I1_ * 8];
__device__ float g_fW1Ac[18 * I1_ * 8];
__device__ float g_fW2c[18 * I2_ * 8];
__device__ float g_gW1Ac[9 * I2_ * 8];

__device__ float g_C1[I1_ * 128], g_d1[I1_];
__device__ float g_C0[I2_ * 3],   g_d0[I2_];

__device__ float g_Tx[B_ * DIM_ * N2_];
__device__ float g_T2t[BQ_ * N2_ * I1_];
__device__ float g_s1t[B_ * N1_ * I1_];    // n-major, bias folded
__device__ float g_T4t[BQ_ * N1_ * I2_];

__device__ int   g_idx1[B_ * N1_ * 3];
__device__ float g_wt1 [B_ * N1_ * 3];
__device__ int   g_idx2[B_ * N0_ * 3];
__device__ float g_wt2 [B_ * N0_ * 3];

// ---------------------------------------------------------------------------
// Prep kernel — flattened dispatch, 738 blocks
// ---------------------------------------------------------------------------
__global__ __launch_bounds__(256)
void prep_kernel(
    const float* __restrict__ w1, const float* __restrict__ b1, const float* __restrict__ bn1,
    const float* __restrict__ w2, const float* __restrict__ b2, const float* __restrict__ bn2,
    const float* __restrict__ fw1, const float* __restrict__ fb1, const float* __restrict__ fbn1,
    const float* __restrict__ fw2, const float* __restrict__ fb2, const float* __restrict__ fbn2,
    const float* __restrict__ gw1, const float* __restrict__ gb1, const float* __restrict__ gbn1,
    const float* __restrict__ gw2, const float* __restrict__ gb2, const float* __restrict__ gbn2,
    const float* __restrict__ a1_w, const float* __restrict__ a1_b,
    const float* __restrict__ a2_w, const float* __restrict__ a2_b,
    float* __restrict__ W1f, float* __restrict__ b1f,
    float* __restrict__ W2c, float* __restrict__ b2f,
    float* __restrict__ fW1Ac, float* __restrict__ fb1f,
    float* __restrict__ fW2c, float* __restrict__ fb2f,
    float* __restrict__ gW1Ac, float* __restrict__ gb1f,
    float* __restrict__ gW2f, float* __restrict__ gb2f,
    float* __restrict__ C1, float* __restrict__ d1,
    float* __restrict__ C0, float* __restrict__ d0)
{
    int id = blockIdx.x;
    int cs, bb;
    if      (id < 343) { cs = 0; bb = id; }
    else if (id < 510) { cs = 1; bb = id - 343; }
    else if (id < 591) { cs = 2; bb = id - 510; }
    else if (id < 632) { cs = 3; bb = id - 591; }
    else if (id < 653) { cs = 4; bb = id - 632; }
    else if (id < 664) { cs = 5; bb = id - 653; }
    else if (id < 736) { cs = 6; bb = id - 664; }
    else               { cs = 7; bb = id - 736; }
    int t = bb * 256 + threadIdx.x;
    switch (cs) {
    case 0: {
        if (t < DIM_ * DIM_) {
            int m = t / DIM_;
            float s = bn1[m] * rsqrtf(bn1[3 * DIM_ + m] + EPS_);
            W1f[t] = w1[t] * s;
        }
        if (t < DIM_) {
            float s = bn1[t] * rsqrtf(bn1[3 * DIM_ + t] + EPS_);
            b1f[t] = s * (b1[t] - bn1[2 * DIM_ + t]) + bn1[DIM_ + t];
        }
    } break;
    case 1: {
        if (t < 37 * I1_ * 8) {
            int kc = t / (I1_ * 8), r = t % (I1_ * 8), m = r / 8, k = r % 8;
            int gk = kc * 8 + k;
            float s = bn2[m] * rsqrtf(bn2[3 * I1_ + m] + EPS_);
            W2c[t] = w2[m * DIM_ + gk] * s;
        }
        if (t < I1_) {
            float s = bn2[t] * rsqrtf(bn2[3 * I1_ + t] + EPS_);
            b2f[t] = s * (b2[t] - bn2[2 * I1_ + t]) + bn2[I1_ + t];
        }
    } break;
    case 2: {
        if (t < 18 * I1_ * 8) {
            int kc = t / (I1_ * 8), r = t % (I1_ * 8), m = r / 8, k = r % 8;
            int gk = kc * 8 + k;
            float s = fbn1[m] * rsqrtf(fbn1[3 * I1_ + m] + EPS_);
            fW1Ac[t] = fw1[m * (2 * I1_) + gk] * s;
        }
        if (t < I1_) {
            float s = fbn1[t] * rsqrtf(fbn1[3 * I1_ + t] + EPS_);
            fb1f[t] = s * (fb1[t] - fbn1[2 * I1_ + t]) + fbn1[I1_ + t];
        }
    } break;
    case 3: {
        if (t < 18 * I2_ * 8) {
            int kc = t / (I2_ * 8), r = t % (I2_ * 8), m = r / 8, k = r % 8;
            int gk = kc * 8 + k;
            float s = fbn2[m] * rsqrtf(fbn2[3 * I2_ + m] + EPS_);
            fW2c[t] = fw2[m * I1_ + gk] * s;
        }
        if (t < I2_) {
            float s = fbn2[t] * rsqrtf(fbn2[3 * I2_ + t] + EPS_);
            fb2f[t] = s * (fb2[t] - fbn2[2 * I2_ + t]) + fbn2[I2_ + t];
        }
    } break;
    case 4: {
        if (t < 9 * I2_ * 8) {
            int kc = t / (I2_ * 8), r = t % (I2_ * 8), m = r / 8, k = r % 8;
            int gk = kc * 8 + k;
            float s = gbn1[m] * rsqrtf(gbn1[3 * I2_ + m] + EPS_);
            gW1Ac[t] = gw1[m * (2 * I2_) + gk] * s;
        }
        if (t < I2_) {
            float s = gbn1[t] * rsqrtf(gbn1[3 * I2_ + t] + EPS_);
            gb1f[t] = s * (gb1[t] - gbn1[2 * I2_ + t]) + gbn1[I2_ + t];
        }
    } break;
    case 5: {
        if (t < I3_ * I2_) {
            int m = t / I2_;
            float s = gbn2[m] * rsqrtf(gbn2[3 * I3_ + m] + EPS_);
            gW2f[t] = gw2[t] * s;
        }
        if (t < I3_) {
            float s = gbn2[t] * rsqrtf(gbn2[3 * I3_ + t] + EPS_);
            gb2f[t] = s * (gb2[t] - gbn2[2 * I3_ + t]) + gbn2[I3_ + t];
        }
    } break;
    case 6: {
        if (t < I1_ * 128) {
            int o = t / 128, k = t % 128;
            float s = fbn1[o] * rsqrtf(fbn1[3 * I1_ + o] + EPS_);
            float acc = 0.f;
            for (int c = 0; c < I1_; c++)
                acc += fw1[o * (2 * I1_) + I1_ + c] * a2_w[c * 128 + k];
            C1[t] = acc * s;
        }
        if (t < I1_) {
            float s = fbn1[t] * rsqrtf(fbn1[3 * I1_ + t] + EPS_);
            float acc = 0.f;
            for (int c = 0; c < I1_; c++)
                acc += fw1[t * (2 * I1_) + I1_ + c] * a2_b[c];
            d1[t] = acc * s;
        }
    } break;
    case 7: {
        if (t < I2_ * 3) {
            int o = t / 3, k = t % 3;
            float s = gbn1[o] * rsqrtf(gbn1[3 * I2_ + o] + EPS_);
            float acc = 0.f;
            for (int c = 0; c < I2_; c++)
                acc += gw1[o * (2 * I2_) + I2_ + c] * a1_w[c * 3 + k];
            C0[t] = acc * s;
        }
        if (t >= I2_ * 3 && t < I2_ * 4) {
            int o = t - I2_ * 3;
            float s = gbn1[o] * rsqrtf(gbn1[3 * I2_ + o] + EPS_);
            float acc = 0.f;
            for (int c = 0; c < I2_; c++)
                acc += gw1[o * (2 * I2_) + I2_ + c] * a1_b[c];
            d0[o] = acc * s;
        }
    } break;
    }
}

// ---------------------------------------------------------------------------
// GEMM body (256 threads). TOUT: write Y transposed n-major with bias folded.
// ---------------------------------------------------------------------------
template <int BM, int BN, int BK, int TM, int TN, bool TOUT>
__device__ __forceinline__
void gemm_body(float* sm,
               const float* __restrict__ W, int ldw,
               const float* __restrict__ X,
               float* __restrict__ Y,
               const float* __restrict__ biasA,
               const float* __restrict__ biasB,
               int M, int N, int K, int bx, int by, int b, int Mfull) {
    const int TX = BN / TN;
    float* Ws = sm;
    float* Xs = sm + BK * BM;
    const int m0 = by * BM;
    const int n0 = bx * BN;
    const float* Xb = X + (size_t)b * K * N;

    const int tid = threadIdx.x;
    const int tx = tid % TX, ty = tid / TX;
    const int tm = ty * TM, tn = tx * TN;

    float acc[TM][TN];
#pragma unroll
    for (int i = 0; i < TM; i++)
#pragma unroll
        for (int j = 0; j < TN; j++) acc[i][j] = 0.f;

    for (int k0 = 0; k0 < K; k0 += BK) {
#pragma unroll
        for (int i = tid; i < BM * BK; i += 256) {
            int m = i / BK, k = i % BK;
            int gm = m0 + m, gk = k0 + k;
            Ws[k * BM + m] = (gm < M) ? W[(size_t)gm * ldw + gk] : 0.f;
        }
#pragma unroll
        for (int i = tid; i < BK * BN; i += 256) {
            int k = i / BN, n = i % BN;
            Xs[k * BN + n] = Xb[(size_t)(k0 + k) * N + n0 + n];
        }
        __syncthreads();
#pragma unroll
        for (int kk = 0; kk < BK; kk++) {
            float a[TM], xv[TN];
#pragma unroll
            for (int i = 0; i < TM; i++) a[i] = Ws[kk * BM + tm + i];
#pragma unroll
            for (int j = 0; j < TN; j++) xv[j] = Xs[kk * BN + tn + j];
#pragma unroll
            for (int i = 0; i < TM; i++)
#pragma unroll
                for (int j = 0; j < TN; j++) acc[i][j] = fmaf(a[i], xv[j], acc[i][j]);
        }
        __syncthreads();
    }
    if (!TOUT) {
        float* Yb = Y + (size_t)b * M * N;
#pragma unroll
        for (int i = 0; i < TM; i++) {
            int m = m0 + tm + i;
            if (m >= M) break;
#pragma unroll
            for (int j = 0; j < TN; j++)
                Yb[(size_t)m * N + n0 + tn + j] = acc[i][j];
        }
    } else {
#pragma unroll
        for (int i = 0; i < TM; i++) {
            float bv = biasA[m0 + tm + i] + biasB[m0 + tm + i];
#pragma unroll
            for (int j = 0; j < TN; j++)
                sm[(tn + j) * (BM + 1) + tm + i] = acc[i][j] + bv;
        }
        __syncthreads();
        float* Yb = Y + (size_t)b * N * Mfull;
        for (int e = tid; e < BN * BM; e += 256) {
            int n = e / BM, m = e % BM;
            Yb[(size_t)(n0 + n) * Mfull + m0 + m] = sm[n * (BM + 1) + m];
        }
    }
}

// ---------------------------------------------------------------------------
// three_nn body (256 threads)
// ---------------------------------------------------------------------------
__device__ __forceinline__
void three_nn_body(float* sm, int id2,
                   const float* __restrict__ sa0_xyz,
                   const float* __restrict__ sa1_xyz,
                   const float* __restrict__ sa2_xyz,
                   int* __restrict__ idx1, float* __restrict__ wt1,
                   int* __restrict__ idx2, float* __restrict__ wt2) {
    float* kx = sm;
    float* ky = sm + 1024;
    float* kz = sm + 2048;
    float* cd = sm + 3072;
    int*   ci = (int*)(sm + 3840);

    int lvl, bx, b;
    if (id2 < 32) { lvl = 0; bx = id2 & 15; b = id2 >> 4; }
    else          { int id3 = id2 - 32; lvl = 1; bx = id3 & 63; b = id3 >> 6; }
    const int NK = lvl ? 1024 : 256;
    const int Nu = lvl ? N0_ : N1_;
    const int CS = NK / 4;
    const float* unknown = lvl ? sa0_xyz : sa1_xyz;
    const float* known   = lvl ? sa1_xyz : sa2_xyz;
    int*   idx = lvl ? idx2 : idx1;
    float* w   = lvl ? wt2  : wt1;

    const float* kb = known + (size_t)b * NK * 3;
    for (int i = threadIdx.x; i < NK; i += 256) {
        kx[i] = kb[i * 3 + 0];
        ky[i] = kb[i * 3 + 1];
        kz[i] = kb[i * 3 + 2];
    }
    __syncthreads();

    int ul = threadIdx.x & 63;
    int ch = threadIdx.x >> 6;
    int u = bx * 64 + ul;
    const float* up = unknown + ((size_t)b * Nu + u) * 3;
    float ux = up[0], uy = up[1], uz = up[2];

    float d0 = 3.4e38f, d1 = 3.4e38f, d2 = 3.4e38f;
    int i0 = 0, i1 = 0, i2 = 0;
    int base = ch * CS;
#pragma unroll 4
    for (int t = 0; t < CS; t++) {
        int i = base + t;
        float dx = ux - kx[i], dy = uy - ky[i], dz = uz - kz[i];
        float d = fmaf(dx, dx, fmaf(dy, dy, dz * dz));
        if (d < d2) {
            if (d < d0)      { d2 = d1; i2 = i1; d1 = d0; i1 = i0; d0 = d; i0 = i; }
            else if (d < d1) { d2 = d1; i2 = i1; d1 = d;  i1 = i; }
            else             { d2 = d;  i2 = i; }
        }
    }
    cd[(ul * 4 + ch) * 3 + 0] = d0; cd[(ul * 4 + ch) * 3 + 1] = d1; cd[(ul * 4 + ch) * 3 + 2] = d2;
    ci[(ul * 4 + ch) * 3 + 0] = i0; ci[(ul * 4 + ch) * 3 + 1] = i1; ci[(ul * 4 + ch) * 3 + 2] = i2;
    __syncthreads();

    if (threadIdx.x < 64) {
        int uu = bx * 64 + threadIdx.x;
        float m0 = 3.4e38f, m1 = 3.4e38f, m2 = 3.4e38f;
        int j0 = 0, j1 = 0, j2 = 0;
#pragma unroll
        for (int c = 0; c < 4; c++) {
#pragma unroll
            for (int t = 0; t < 3; t++) {
                float d = cd[(threadIdx.x * 4 + c) * 3 + t];
                int i = ci[(threadIdx.x * 4 + c) * 3 + t];
                if (d < m2) {
                    if (d < m0)      { m2 = m1; j2 = j1; m1 = m0; j1 = j0; m0 = d; j0 = i; }
                    else if (d < m1) { m2 = m1; j2 = j1; m1 = d;  j1 = i; }
                    else             { m2 = d;  j2 = i; }
                }
            }
        }
        float w0 = 1.f / (m0 + 1e-8f);
        float w1 = 1.f / (m1 + 1e-8f);
        float w2 = 1.f / (m2 + 1e-8f);
        float ws = w0 + w1 + w2;
        size_t o = ((size_t)b * Nu + uu) * 3;
        idx[o] = j0; idx[o + 1] = j1; idx[o + 2] = j2;
        w[o] = w0 / ws; w[o + 1] = w1 / ws; w[o + 2] = w2 / ws;
    }
}

// ---------------------------------------------------------------------------
// util kernel: Tx GEMM (40) + s1t GEMM (96, transposed+bias) + three_nn (160)
// ---------------------------------------------------------------------------
__global__ __launch_bounds__(256)
void util_kernel(const float* __restrict__ W1f,
                 const float* __restrict__ x,
                 float* __restrict__ Tx,
                 const float* __restrict__ C1,
                 const float* __restrict__ sa1f,
                 float* __restrict__ s1t,
                 const float* __restrict__ fb1f,
                 const float* __restrict__ d1v,
                 const float* __restrict__ sa0_xyz,
                 const float* __restrict__ sa1_xyz,
                 const float* __restrict__ sa2_xyz,
                 int* __restrict__ idx1, float* __restrict__ wt1,
                 int* __restrict__ idx2, float* __restrict__ wt2) {
    __shared__ float sm[4608];
    int id = blockIdx.x;
    if (id < 40) {
        int bx = id & 3, r = id >> 2, by = r % 5, b = r / 5;
        gemm_body<64, 64, 16, 4, 4, false>(sm, W1f, DIM_, x, Tx, nullptr, nullptr,
                                           DIM_, N2_, CTX_, bx, by, b, 0);
    } else if (id < 136) {
        int id1 = id - 40;
        int bx = id1 & 15, r = id1 >> 4, by = r % 3, b = r / 3;
        gemm_body<48, 64, 16, 3, 4, true>(sm, C1, 128, sa1f, s1t, fb1f, d1v,
                                          I1_, N1_, 128, bx, by, b, I1_);
    } else {
        three_nn_body(sm, id - 136, sa0_xyz, sa1_xyz, sa2_xyz, idx1, wt1, idx2, wt2);
    }
}

// ---------------------------------------------------------------------------
// fusedA: n-tile 16 -> grid (16, 32) = 512 blocks, 128 threads.
// Micro-tile 9x2 (TX=8, TY=16). Weights via L1 LDG. Xs double-buffered.
// ---------------------------------------------------------------------------
__global__ __launch_bounds__(128)
void fusedA_kernel(const float* __restrict__ W2c,    // (37,144,8)
                   const float* __restrict__ b2f,
                   const float* __restrict__ fW1Ac,  // (18,144,8)
                   const float* __restrict__ Tx,     // (2,296,256)
                   const float* __restrict__ maskg,  // (32,8,256)
                   const float* __restrict__ W1f,    // (296,296)
                   const float* __restrict__ b1f,
                   float* __restrict__ T2t) {        // (32,256,144)
    __shared__ float Xp[2][128];      // [k8][n16]
    __shared__ float Hs[144 * 20];    // [c][n16] pad 20

    const int bq = blockIdx.y, b = bq >> 4;
    const int n0 = blockIdx.x * 16;
    const int tid = threadIdx.x;
    const int tx = tid & 7, ty = tid >> 3;
    const int tm = ty * 9, tn = tx * 2;

    const int kl = tid >> 4, nl = tid & 15;   // Xs slot owner
    float mv[8];
#pragma unroll
    for (int j = 0; j < 8; j++)
        mv[j] = __ldg(maskg + ((size_t)bq * 8 + j) * N2_ + n0 + nl);
    const float* Txb = Tx + (size_t)b * DIM_ * N2_ + n0 + nl;

    float acc[9][2];
#pragma unroll
    for (int i = 0; i < 9; i++) { acc[i][0] = 0.f; acc[i][1] = 0.f; }

    auto h1v = [&](int gk) -> float {
        const float4* wp = (const float4*)(W1f + (size_t)gk * DIM_ + CTX_);
        float4 wa = __ldg(wp), wb = __ldg(wp + 1);
        float v = __ldg(Txb + (size_t)gk * N2_) + __ldg(b1f + gk);
        v += wa.x * mv[0] + wa.y * mv[1] + wa.z * mv[2] + wa.w * mv[3]
           + wb.x * mv[4] + wb.y * mv[5] + wb.z * mv[6] + wb.w * mv[7];
        return fmaxf(v, 0.f);
    };

    // ---- phase 1: H = ReLU(W2*h1 + b2), 37 chunks, Xs dbuf, weights via LDG
    float xv;
    Xp[0][tid] = h1v(kl);

    for (int kc = 0; kc < 37; kc++) {
        __syncthreads();
        const int cur = kc & 1, nxt = cur ^ 1;
        const bool more = (kc + 1 < 37);
        if (more) xv = h1v((kc + 1) * 8 + kl);
        const float* Xs = Xp[cur];
        const float4* wg = (const float4*)(W2c + (size_t)kc * 1152);
#pragma unroll
        for (int g = 0; g < 2; g++) {
            float4 a4[9];
#pragma unroll
            for (int i = 0; i < 9; i++)
                a4[i] = __ldg(wg + (tm + i) * 2 + g);
            float2 x0 = *(const float2*)&Xs[(g * 4 + 0) * 16 + tn];
            float2 x1 = *(const float2*)&Xs[(g * 4 + 1) * 16 + tn];
            float2 x2 = *(const float2*)&Xs[(g * 4 + 2) * 16 + tn];
            float2 x3 = *(const float2*)&Xs[(g * 4 + 3) * 16 + tn];
#pragma unroll
            for (int i = 0; i < 9; i++) {
                acc[i][0] = fmaf(a4[i].x, x0.x, acc[i][0]);
                acc[i][1] = fmaf(a4[i].x, x0.y, acc[i][1]);
                acc[i][0] = fmaf(a4[i].y, x1.x, acc[i][0]);
                acc[i][1] = fmaf(a4[i].y, x1.y, acc[i][1]);
                acc[i][0] = fmaf(a4[i].z, x2.x, acc[i][0]);
                acc[i][1] = fmaf(a4[i].z, x2.y, acc[i][1]);
                acc[i][0] = fmaf(a4[i].w, x3.x, acc[i][0]);
                acc[i][1] = fmaf(a4[i].w, x3.y, acc[i][1]);
            }
        }
        if (more) Xp[nxt][tid] = xv;
    }
    // bias + relu -> Hs
#pragma unroll
    for (int i = 0; i < 9; i++) {
        float bv = __ldg(b2f + tm + i);
        float2 hv;
        hv.x = fmaxf(acc[i][0] + bv, 0.f);
        hv.y = fmaxf(acc[i][1] + bv, 0.f);
        *(float2*)&Hs[(tm + i) * 20 + tn] = hv;
    }
    __syncthreads();

    // ---- phase 2: T2 = fW1A * H, 18 chunks, barrier-free, weights via LDG
    float acc2[9][2];
#pragma unroll
    for (int i = 0; i < 9; i++) { acc2[i][0] = 0.f; acc2[i][1] = 0.f; }

    for (int kc = 0; kc < 18; kc++) {
        const float4* wg = (const float4*)(fW1Ac + (size_t)kc * 1152);
        int kb = kc * 8;
#pragma unroll
        for (int g = 0; g < 2; g++) {
            float4 a4[9];
#pragma unroll
            for (int i = 0; i < 9; i++)
                a4[i] = __ldg(wg + (tm + i) * 2 + g);
            float2 x0 = *(const float2*)&Hs[(kb + g * 4 + 0) * 20 + tn];
            float2 x1 = *(const float2*)&Hs[(kb + g * 4 + 1) * 20 + tn];
            float2 x2 = *(const float2*)&Hs[(kb + g * 4 + 2) * 20 + tn];
            float2 x3 = *(const float2*)&Hs[(kb + g * 4 + 3) * 20 + tn];
#pragma unroll
            for (int i = 0; i < 9; i++) {
                acc2[i][0] = fmaf(a4[i].x, x0.x, acc2[i][0]);
                acc2[i][1] = fmaf(a4[i].x, x0.y, acc2[i][1]);
                acc2[i][0] = fmaf(a4[i].y, x1.x, acc2[i][0]);
                acc2[i][1] = fmaf(a4[i].y, x1.y, acc2[i][1]);
                acc2[i][0] = fmaf(a4[i].z, x2.x, acc2[i][0]);
                acc2[i][1] = fmaf(a4[i].z, x2.y, acc2[i][1]);
                acc2[i][0] = fmaf(a4[i].w, x3.x, acc2[i][0]);
                acc2[i][1] = fmaf(a4[i].w, x3.y, acc2[i][1]);
            }
        }
    }
#pragma unroll
    for (int j = 0; j < 2; j++) {
        size_t base = ((size_t)bq * N2_ + n0 + tn + j) * I1_ + tm;
#pragma unroll
        for (int i = 0; i < 9; i++) T2t[base + i] = acc2[i][j];
    }
}

// ---------------------------------------------------------------------------
// fusedB: n-tile 32 -> grid (32, 32) = 1024 blocks, 128 threads.
// Micro-tile 9x2 (TX=16, TY=8). Warp-contiguous gather into float4-level
// XOR-swizzled smem (rows of 32); weights via L1 LDG; 3 barriers.
// Swizzle: element (c, nu) at c*32 + (((nu>>2) ^ ((c>>2)&7))<<2) + (nu&3)
// ---------------------------------------------------------------------------
__global__ __launch_bounds__(128)
void fusedB_kernel(const float* __restrict__ T2t,    // (32,256,144)
                   const int* __restrict__ idx1,
                   const float* __restrict__ wt1,
                   const float* __restrict__ s1t,    // (2,1024,144) bias folded
                   const float* __restrict__ fW2c,   // (18,72,8)
                   const float* __restrict__ fb2f,
                   const float* __restrict__ gW1Ac,  // (9,72,8)
                   float* __restrict__ T4t) {        // (32,1024,72)
    extern __shared__ float smem[];
    float* H3s = smem;                 // 144 x 32 swizzled

    const int bq = blockIdx.y, b = bq >> 4;
    const int n0 = blockIdx.x * 32;
    const int tid = threadIdx.x;
    const int warp = tid >> 5, lane = tid & 31;

    // ---- gather: warp handles 8 nu, lanes span channels (contiguous rows)
#pragma unroll 2
    for (int t = 0; t < 8; t++) {
        int nu = warp * 8 + t;
        size_t o = ((size_t)b * N1_ + n0 + nu) * 3;
        int j0 = __ldg(idx1 + o), j1 = __ldg(idx1 + o + 1), j2 = __ldg(idx1 + o + 2);
        float w0 = __ldg(wt1 + o), w1 = __ldg(wt1 + o + 1), w2 = __ldg(wt1 + o + 2);
        const float4* p0 = (const float4*)(T2t + ((size_t)bq * N2_ + j0) * I1_);
        const float4* p1 = (const float4*)(T2t + ((size_t)bq * N2_ + j1) * I1_);
        const float4* p2 = (const float4*)(T2t + ((size_t)bq * N2_ + j2) * I1_);
        const float4* ps = (const float4*)(s1t + ((size_t)b * N1_ + n0 + nu) * I1_);
        {
            float4 a0 = __ldg(p0 + lane), a1 = __ldg(p1 + lane),
                   a2 = __ldg(p2 + lane), s  = __ldg(ps + lane);
            int c = lane * 4;                     // (c>>2)&7 == lane&7
            int off = c * 32 + ((((nu >> 2) ^ (lane & 7)) << 2) | (nu & 3));
            H3s[off + 0 * 32] = fmaxf(w0 * a0.x + w1 * a1.x + w2 * a2.x + s.x, 0.f);
            H3s[off + 1 * 32] = fmaxf(w0 * a0.y + w1 * a1.y + w2 * a2.y + s.y, 0.f);
            H3s[off + 2 * 32] = fmaxf(w0 * a0.z + w1 * a1.z + w2 * a2.z + s.z, 0.f);
            H3s[off + 3 * 32] = fmaxf(w0 * a0.w + w1 * a1.w + w2 * a2.w + s.w, 0.f);
        }
        if (lane < 4) {
            float4 a0 = __ldg(p0 + 32 + lane), a1 = __ldg(p1 + 32 + lane),
                   a2 = __ldg(p2 + 32 + lane), s  = __ldg(ps + 32 + lane);
            int c = 128 + lane * 4;               // (c>>2)&7 == lane (lane<4)
            int off = c * 32 + ((((nu >> 2) ^ lane) << 2) | (nu & 3));
            H3s[off + 0 * 32] = fmaxf(w0 * a0.x + w1 * a1.x + w2 * a2.x + s.x, 0.f);
            H3s[off + 1 * 32] = fmaxf(w0 * a0.y + w1 * a1.y + w2 * a2.y + s.y, 0.f);
            H3s[off + 2 * 32] = fmaxf(w0 * a0.z + w1 * a1.z + w2 * a2.z + s.z, 0.f);
            H3s[off + 3 * 32] = fmaxf(w0 * a0.w + w1 * a1.w + w2 * a2.w + s.w, 0.f);
        }
    }
    __syncthreads();   // gather complete

    const int tx = tid & 15, ty = tid >> 4;   // 16 x 8
    const int tm = ty * 9, tn = tx * 2;
    const int hslot = tx >> 1;                // float4 slot index of tn
    const int hsub = (tx & 1) << 1;           // offset within float4

    // ---- phase 1: acc = fW2 * H3, K=144 (18 chunks), barrier-free
    float acc[9][2];
#pragma unroll
    for (int i = 0; i < 9; i++) { acc[i][0] = 0.f; acc[i][1] = 0.f; }

    for (int kc = 0; kc < 18; kc++) {
        const float4* wg = (const float4*)(fW2c + (size_t)kc * 576);
        int kb = kc * 8;
#pragma unroll
        for (int g = 0; g < 2; g++) {
            int xsl = (2 * kc + g) & 7;
            int xof = (((hslot ^ xsl) << 2) | hsub);
            float4 a4[9];
#pragma unroll
            for (int i = 0; i < 9; i++)
                a4[i] = __ldg(wg + (tm + i) * 2 + g);
            float2 x0 = *(const float2*)&H3s[(kb + g * 4 + 0) * 32 + xof];
            float2 x1 = *(const float2*)&H3s[(kb + g * 4 + 1) * 32 + xof];
            float2 x2 = *(const float2*)&H3s[(kb + g * 4 + 2) * 32 + xof];
            float2 x3 = *(const float2*)&H3s[(kb + g * 4 + 3) * 32 + xof];
#pragma unroll
            for (int i = 0; i < 9; i++) {
                acc[i][0] = fmaf(a4[i].x, x0.x, acc[i][0]);
                acc[i][1] = fmaf(a4[i].x, x0.y, acc[i][1]);
                acc[i][0] = fmaf(a4[i].y, x1.x, acc[i][0]);
                acc[i][1] = fmaf(a4[i].y, x1.y, acc[i][1]);
                acc[i][0] = fmaf(a4[i].z, x2.x, acc[i][0]);
                acc[i][1] = fmaf(a4[i].z, x2.y, acc[i][1]);
                acc[i][0] = fmaf(a4[i].w, x3.x, acc[i][0]);
                acc[i][1] = fmaf(a4[i].w, x3.y, acc[i][1]);
            }
        }
    }
    __syncthreads();   // all phase-1 H3s reads done -> safe to overlay

    // bias + relu -> overlay into H3s rows 0..71 (same swizzle)
#pragma unroll
    for (int i = 0; i < 9; i++) {
        float bv = __ldg(fb2f + tm + i);
        int c = tm + i;
        int off = c * 32 + ((((tn >> 2) ^ ((c >> 2) & 7)) << 2) | (tn & 3));
        float2 hv;
        hv.x = fmaxf(acc[i][0] + bv, 0.f);
        hv.y = fmaxf(acc[i][1] + bv, 0.f);
        *(float2*)&H3s[off] = hv;
    }
    __syncthreads();   // overlay visible

    // ---- phase 2: T4 = gW1A * Hs, K=72 (9 chunks), barrier-free
    float acc2[9][2];
#pragma unroll
    for (int i = 0; i < 9; i++) { acc2[i][0] = 0.f; acc2[i][1] = 0.f; }

    for (int kc = 0; kc < 9; kc++) {
        const float4* wg = (const float4*)(gW1Ac + (size_t)kc * 576);
        int kb = kc * 8;
#pragma unroll
        for (int g = 0; g < 2; g++) {
            int xsl = (2 * kc + g) & 7;
            int xof = (((hslot ^ xsl) << 2) | hsub);
            float4 a4[9];
#pragma unroll
            for (int i = 0; i < 9; i++)
                a4[i] = __ldg(wg + (tm + i) * 2 + g);
            float2 x0 = *(const float2*)&H3s[(kb + g * 4 + 0) * 32 + xof];
            float2 x1 = *(const float2*)&H3s[(kb + g * 4 + 1) * 32 + xof];
            float2 x2 = *(const float2*)&H3s[(kb + g * 4 + 2) * 32 + xof];
            float2 x3 = *(const float2*)&H3s[(kb + g * 4 + 3) * 32 + xof];
#pragma unroll
            for (int i = 0; i < 9; i++) {
                acc2[i][0] = fmaf(a4[i].x, x0.x, acc2[i][0]);
                acc2[i][1] = fmaf(a4[i].x, x0.y, acc2[i][1]);
                acc2[i][0] = fmaf(a4[i].y, x1.x, acc2[i][0]);
                acc2[i][1] = fmaf(a4[i].y, x1.y, acc2[i][1]);
                acc2[i][0] = fmaf(a4[i].z, x2.x, acc2[i][0]);
                acc2[i][1] = fmaf(a4[i].z, x2.y, acc2[i][1]);
                acc2[i][0] = fmaf(a4[i].w, x3.x, acc2[i][0]);
                acc2[i][1] = fmaf(a4[i].w, x3.y, acc2[i][1]);
            }
        }
    }
#pragma unroll
    for (int j = 0; j < 2; j++) {
        size_t base = ((size_t)bq * N1_ + n0 + tn + j) * I2_ + tm;
#pragma unroll
        for (int i = 0; i < 9; i++) T4t[base + i] = acc2[i][j];
    }
}

// ---------------------------------------------------------------------------
// final: warp-contiguous gather into swizzled smem Hv[72][128], then
// per-thread FP2-L2 + projection. 128 threads, grid (32, 32).
// ---------------------------------------------------------------------------
__global__ __launch_bounds__(128)
void final_fuse_kernel(const float* __restrict__ T4t,
                       const int* __restrict__ idx,
                       const float* __restrict__ wt,
                       const float* __restrict__ sa0f,
                       const float* __restrict__ C0,
                       const float* __restrict__ d0v,
                       const float* __restrict__ gb1,
                       const float* __restrict__ gW2,
                       const float* __restrict__ gb2,
                       const float* __restrict__ ow,
                       const float* __restrict__ ob,
                       float* __restrict__ out) {
    extern __shared__ float smem[];
    float* Hv  = smem;                   // 72 x 128 swizzled = 9216
    float* gT  = smem + 9216;            // 72*36 = 2592
    float* gbs = smem + 9216 + 2592;     // 36
    float* ows = gbs + 36;               // 36

    const int tid = threadIdx.x;
    const int warp = tid >> 5, lane = tid & 31;
    const int bq = blockIdx.y, b = bq >> 4;
    const int n0 = blockIdx.x * 128;

    for (int e = tid; e < I2_ * I3_; e += 128) {
        int c = e / I3_, m = e % I3_;
        gT[e] = gW2[m * I2_ + c];
    }
    if (tid < I3_) { gbs[tid] = gb2[tid]; ows[tid] = ow[tid]; }

    float c00[4], c01[4], c02[4], bb4[4];
    if (lane < 18) {
        int c = lane * 4;
#pragma unroll
        for (int r = 0; r < 4; r++) {
            c00[r] = __ldg(C0 + (c + r) * 3 + 0);
            c01[r] = __ldg(C0 + (c + r) * 3 + 1);
            c02[r] = __ldg(C0 + (c + r) * 3 + 2);
            bb4[r] = __ldg(d0v + c + r) + __ldg(gb1 + c + r);
        }
    }

#pragma unroll 2
    for (int t = 0; t < 32; t++) {
        int nu = warp * 32 + t;
        if (lane < 18) {
            size_t o = ((size_t)b * N0_ + n0 + nu) * 3;
            int j0 = __ldg(idx + o), j1 = __ldg(idx + o + 1), j2 = __ldg(idx + o + 2);
            float w0 = __ldg(wt + o), w1 = __ldg(wt + o + 1), w2 = __ldg(wt + o + 2);
            float4 a0 = __ldg((const float4*)(T4t + ((size_t)bq * N1_ + j0) * I2_) + lane);
            float4 a1 = __ldg((const float4*)(T4t + ((size_t)bq * N1_ + j1) * I2_) + lane);
            float4 a2 = __ldg((const float4*)(T4t + ((size_t)bq * N1_ + j2) * I2_) + lane);
            float f0 = __ldg(sa0f + ((size_t)b * 3 + 0) * N0_ + n0 + nu);
            float f1 = __ldg(sa0f + ((size_t)b * 3 + 1) * N0_ + n0 + nu);
            float f2 = __ldg(sa0f + ((size_t)b * 3 + 2) * N0_ + n0 + nu);
            int c = lane * 4;
            int jj = ((((nu >> 2) ^ lane) << 2) | (nu & 3));
            Hv[(c + 0) * 128 + jj] = fmaxf(w0 * a0.x + w1 * a1.x + w2 * a2.x + c00[0] * f0 + c01[0] * f1 + c02[0] * f2 + bb4[0], 0.f);
            Hv[(c + 1) * 128 + jj] = fmaxf(w0 * a0.y + w1 * a1.y + w2 * a2.y + c00[1] * f0 + c01[1] * f1 + c02[1] * f2 + bb4[1], 0.f);
            Hv[(c + 2) * 128 + jj] = fmaxf(w0 * a0.z + w1 * a1.z + w2 * a2.z + c00[2] * f0 + c01[2] * f1 + c02[2] * f2 + bb4[2], 0.f);
            Hv[(c + 3) * 128 + jj] = fmaxf(w0 * a0.w + w1 * a1.w + w2 * a2.w + c00[3] * f0 + c01[3] * f1 + c02[3] * f2 + bb4[3], 0.f);
        }
    }
    __syncthreads();

    const int nu = tid;
    float acc[I3_];
#pragma unroll
    for (int m = 0; m < I3_; m++) acc[m] = 0.f;

#pragma unroll 3
    for (int cc = 0; cc < 18; cc++) {
        int c = cc * 4;
        int jj = ((((nu >> 2) ^ cc) << 2) | (nu & 3));
        float hv[4];
        hv[0] = Hv[(c + 0) * 128 + jj];
        hv[1] = Hv[(c + 1) * 128 + jj];
        hv[2] = Hv[(c + 2) * 128 + jj];
        hv[3] = Hv[(c + 3) * 128 + jj];
#pragma unroll
        for (int q = 0; q < 4; q++) {
            const float4* g4 = (const float4*)&gT[(c + q) * I3_];
#pragma unroll
            for (int mm = 0; mm < 9; mm++) {
                float4 g = g4[mm];
                acc[mm * 4 + 0] = fmaf(g.x, hv[q], acc[mm * 4 + 0]);
                acc[mm * 4 + 1] = fmaf(g.y, hv[q], acc[mm * 4 + 1]);
                acc[mm * 4 + 2] = fmaf(g.z, hv[q], acc[mm * 4 + 2]);
                acc[mm * 4 + 3] = fmaf(g.w, hv[q], acc[mm * 4 + 3]);
            }
        }
    }
    float r = __ldg(ob);
#pragma unroll
    for (int m = 0; m < I3_; m++) r = fmaf(ows[m], fmaxf(acc[m] + gbs[m], 0.f), r);
    out[(size_t)bq * N0_ + n0 + nu] = r;
}

// ---------------------------------------------------------------------------
// Launch
// ---------------------------------------------------------------------------
static inline int cdiv(int a, int b) { return (a + b - 1) / b; }

extern "C" void kernel_launch(void* const* d_in, const int* in_sizes, int n_in,
                              void* d_out, int out_size) {
    const float* x        = (const float*)d_in[0];
    const float* mask     = (const float*)d_in[1];
    const float* sa0_feat = (const float*)d_in[2];
    const float* sa1_feat = (const float*)d_in[3];
    const float* sa0_xyz  = (const float*)d_in[4];
    const float* sa1_xyz  = (const float*)d_in[5];
    const float* sa2_xyz  = (const float*)d_in[6];
    const float* w1       = (const float*)d_in[7];
    const float* b1       = (const float*)d_in[8];
    const float* bn1      = (const float*)d_in[9];
    const float* w2       = (const float*)d_in[10];
    const float* b2       = (const float*)d_in[11];
    const float* bn2      = (const float*)d_in[12];
    const float* a1_w     = (const float*)d_in[13];
    const float* a1_b     = (const float*)d_in[14];
    const float* a2_w     = (const float*)d_in[15];
    const float* a2_b     = (const float*)d_in[16];
    const float* fp1_w1   = (const float*)d_in[17];
    const float* fp1_b1   = (const float*)d_in[18];
    const float* fp1_bn1  = (const float*)d_in[19];
    const float* fp1_w2   = (const float*)d_in[20];
    const float* fp1_b2   = (const float*)d_in[21];
    const float* fp1_bn2  = (const float*)d_in[22];
    const float* fp2_w1   = (const float*)d_in[23];
    const float* fp2_b1   = (const float*)d_in[24];
    const float* fp2_bn1  = (const float*)d_in[25];
    const float* fp2_w2   = (const float*)d_in[26];
    const float* fp2_b2   = (const float*)d_in[27];
    const float* fp2_bn2  = (const float*)d_in[28];
    const float* out_w    = (const float*)d_in[29];
    const float* out_b    = (const float*)d_in[30];
    float* out = (float*)d_out;

    float *W1f, *b1f, *W2c, *b2f, *fW1Ac, *fb1f, *fW2c, *fb2f, *gW1Ac, *gb1f, *gW2f, *gb2f;
    float *C1, *d1, *C0, *d0;
    float *Tx, *T2t, *s1t, *T4t;
    int *idx1, *idx2;
    float *wt1, *wt2;
    cudaGetSymbolAddress((void**)&W1f, g_W1f);     cudaGetSymbolAddress((void**)&b1f, g_b1f);
    cudaGetSymbolAddress((void**)&W2c, g_W2c);     cudaGetSymbolAddress((void**)&b2f, g_b2f);
    cudaGetSymbolAddress((void**)&fW1Ac, g_fW1Ac); cudaGetSymbolAddress((void**)&fb1f, g_fb1f);
    cudaGetSymbolAddress((void**)&fW2c, g_fW2c);   cudaGetSymbolAddress((void**)&fb2f, g_fb2f);
    cudaGetSymbolAddress((void**)&gW1Ac, g_gW1Ac); cudaGetSymbolAddress((void**)&gb1f, g_gb1f);
    cudaGetSymbolAddress((void**)&gW2f, g_gW2f);   cudaGetSymbolAddress((void**)&gb2f, g_gb2f);
    cudaGetSymbolAddress((void**)&C1, g_C1);       cudaGetSymbolAddress((void**)&d1, g_d1);
    cudaGetSymbolAddress((void**)&C0, g_C0);       cudaGetSymbolAddress((void**)&d0, g_d0);
    cudaGetSymbolAddress((void**)&Tx, g_Tx);
    cudaGetSymbolAddress((void**)&T2t, g_T2t);
    cudaGetSymbolAddress((void**)&s1t, g_s1t);
    cudaGetSymbolAddress((void**)&T4t, g_T4t);
    cudaGetSymbolAddress((void**)&idx1, g_idx1);   cudaGetSymbolAddress((void**)&wt1, g_wt1);
    cudaGetSymbolAddress((void**)&idx2, g_idx2);   cudaGetSymbolAddress((void**)&wt2, g_wt2);

    // 1) weight prep
    prep_kernel<<<738, 256>>>(w1, b1, bn1, w2, b2, bn2,
                              fp1_w1, fp1_b1, fp1_bn1, fp1_w2, fp1_b2, fp1_bn2,
                              fp2_w1, fp2_b1, fp2_bn1, fp2_w2, fp2_b2, fp2_bn2,
                              a1_w, a1_b, a2_w, a2_b,
                              W1f, b1f, W2c, b2f, fW1Ac, fb1f, fW2c, fb2f,
                              gW1Ac, gb1f, gW2f, gb2f, C1, d1, C0, d0);
    // 2) util: Tx GEMM + s1t GEMM (transposed, bias folded) + three_nn
    util_kernel<<<296, 256>>>(W1f, x, Tx, C1, sa1_feat, s1t, fb1f, d1,
                              sa0_xyz, sa1_xyz, sa2_xyz,
                              idx1, wt1, idx2, wt2);
    // 3) fusedA (n-tile 16, grid 512)
    {
        dim3 grid(N2_ / 16, BQ_);
        fusedA_kernel<<<grid, 128>>>(W2c, b2f, fW1Ac, Tx, mask, W1f, b1f, T2t);
    }
    // 4) fusedB (n-tile 32, grid 1024)
    {
        const int smem_bytes = (144 * 32) * 4;
        cudaFuncSetAttribute(fusedB_kernel,
                             cudaFuncAttributeMaxDynamicSharedMemorySize, smem_bytes);
        dim3 grid(N1_ / 32, BQ_);
        fusedB_kernel<<<grid, 128, smem_bytes>>>(T2t, idx1, wt1, s1t,
                                                 fW2c, fb2f, gW1Ac, T4t);
    }
    // 5) final
    {
        const int smem_bytes = (9216 + 2592 + 72) * 4;
        cudaFuncSetAttribute(final_fuse_kernel,
                             cudaFuncAttributeMaxDynamicSharedMemorySize, smem_bytes);
        dim3 grid(N0_ / 128, BQ_);
        final_fuse_kernel<<<grid, 128, smem_bytes>>>(T4t, idx2, wt2, sa0_feat,
                                                     C0, d0, gb1f, gW2f, gb2f,
                                                     out_w, out_b, out);
    }
}

// round 12
// speedup vs baseline: 1.1361x; 1.1361x over previous
#include <cuda_runtime.h>
#include <cuda_bf16.h>
#include <math.h>

// ---------------------------------------------------------------------------
// Problem constants
// ---------------------------------------------------------------------------
#define B_    2
#define Q_    16
#define BQ_   32
#define N0_   4096
#define N1_   1024
#define N2_   256
#define DIM_  296
#define CTX_  288
#define HEADS_ 8
#define I1_   144
#define I2_   72
#define I3_   36
#define EPS_  1e-5f

// ---------------------------------------------------------------------------
// Scratch (device globals)
// ---------------------------------------------------------------------------
__device__ float g_W1f[DIM_ * DIM_], g_b1f[DIM_];
__device__ float g_b2f[I1_], g_fb1f[I1_], g_fb2f[I2_], g_gb1f[I2_], g_gb2f[I3_];
__device__ float g_gW2f[I3_ * I2_];

// chunked k-major weights: [kc][m][k8]
__device__ float g_W2c[37 * I1_ * 8];
__device__ float g_fW1Ac[18 * I1_ * 8];
__device__ float g_fW2c[18 * I2_ * 8];
__device__ float g_gW1Ac[9 * I2_ * 8];

__device__ float g_C1[I1_ * 128], g_d1[I1_];
__device__ float g_C0[I2_ * 3],   g_d0[I2_];

__device__ float g_Tx[B_ * DIM_ * N2_];
__device__ float g_T2t[BQ_ * N2_ * I1_];
__device__ float g_s1t[B_ * N1_ * I1_];    // n-major, bias folded
__device__ float g_T4t[BQ_ * N1_ * I2_];

__device__ int   g_idx1[B_ * N1_ * 3];
__device__ float g_wt1 [B_ * N1_ * 3];
__device__ int   g_idx2[B_ * N0_ * 3];
__device__ float g_wt2 [B_ * N0_ * 3];

// ---------------------------------------------------------------------------
// Prep kernel — flattened dispatch, 738 blocks
// ---------------------------------------------------------------------------
__global__ __launch_bounds__(256)
void prep_kernel(
    const float* __restrict__ w1, const float* __restrict__ b1, const float* __restrict__ bn1,
    const float* __restrict__ w2, const float* __restrict__ b2, const float* __restrict__ bn2,
    const float* __restrict__ fw1, const float* __restrict__ fb1, const float* __restrict__ fbn1,
    const float* __restrict__ fw2, const float* __restrict__ fb2, const float* __restrict__ fbn2,
    const float* __restrict__ gw1, const float* __restrict__ gb1, const float* __restrict__ gbn1,
    const float* __restrict__ gw2, const float* __restrict__ gb2, const float* __restrict__ gbn2,
    const float* __restrict__ a1_w, const float* __restrict__ a1_b,
    const float* __restrict__ a2_w, const float* __restrict__ a2_b,
    float* __restrict__ W1f, float* __restrict__ b1f,
    float* __restrict__ W2c, float* __restrict__ b2f,
    float* __restrict__ fW1Ac, float* __restrict__ fb1f,
    float* __restrict__ fW2c, float* __restrict__ fb2f,
    float* __restrict__ gW1Ac, float* __restrict__ gb1f,
    float* __restrict__ gW2f, float* __restrict__ gb2f,
    float* __restrict__ C1, float* __restrict__ d1,
    float* __restrict__ C0, float* __restrict__ d0)
{
    int id = blockIdx.x;
    int cs, bb;
    if      (id < 343) { cs = 0; bb = id; }
    else if (id < 510) { cs = 1; bb = id - 343; }
    else if (id < 591) { cs = 2; bb = id - 510; }
    else if (id < 632) { cs = 3; bb = id - 591; }
    else if (id < 653) { cs = 4; bb = id - 632; }
    else if (id < 664) { cs = 5; bb = id - 653; }
    else if (id < 736) { cs = 6; bb = id - 664; }
    else               { cs = 7; bb = id - 736; }
    int t = bb * 256 + threadIdx.x;
    switch (cs) {
    case 0: {
        if (t < DIM_ * DIM_) {
            int m = t / DIM_;
            float s = bn1[m] * rsqrtf(bn1[3 * DIM_ + m] + EPS_);
            W1f[t] = w1[t] * s;
        }
        if (t < DIM_) {
            float s = bn1[t] * rsqrtf(bn1[3 * DIM_ + t] + EPS_);
            b1f[t] = s * (b1[t] - bn1[2 * DIM_ + t]) + bn1[DIM_ + t];
        }
    } break;
    case 1: {
        if (t < 37 * I1_ * 8) {
            int kc = t / (I1_ * 8), r = t % (I1_ * 8), m = r / 8, k = r % 8;
            int gk = kc * 8 + k;
            float s = bn2[m] * rsqrtf(bn2[3 * I1_ + m] + EPS_);
            W2c[t] = w2[m * DIM_ + gk] * s;
        }
        if (t < I1_) {
            float s = bn2[t] * rsqrtf(bn2[3 * I1_ + t] + EPS_);
            b2f[t] = s * (b2[t] - bn2[2 * I1_ + t]) + bn2[I1_ + t];
        }
    } break;
    case 2: {
        if (t < 18 * I1_ * 8) {
            int kc = t / (I1_ * 8), r = t % (I1_ * 8), m = r / 8, k = r % 8;
            int gk = kc * 8 + k;
            float s = fbn1[m] * rsqrtf(fbn1[3 * I1_ + m] + EPS_);
            fW1Ac[t] = fw1[m * (2 * I1_) + gk] * s;
        }
        if (t < I1_) {
            float s = fbn1[t] * rsqrtf(fbn1[3 * I1_ + t] + EPS_);
            fb1f[t] = s * (fb1[t] - fbn1[2 * I1_ + t]) + fbn1[I1_ + t];
        }
    } break;
    case 3: {
        if (t < 18 * I2_ * 8) {
            int kc = t / (I2_ * 8), r = t % (I2_ * 8), m = r / 8, k = r % 8;
            int gk = kc * 8 + k;
            float s = fbn2[m] * rsqrtf(fbn2[3 * I2_ + m] + EPS_);
            fW2c[t] = fw2[m * I1_ + gk] * s;
        }
        if (t < I2_) {
            float s = fbn2[t] * rsqrtf(fbn2[3 * I2_ + t] + EPS_);
            fb2f[t] = s * (fb2[t] - fbn2[2 * I2_ + t]) + fbn2[I2_ + t];
        }
    } break;
    case 4: {
        if (t < 9 * I2_ * 8) {
            int kc = t / (I2_ * 8), r = t % (I2_ * 8), m = r / 8, k = r % 8;
            int gk = kc * 8 + k;
            float s = gbn1[m] * rsqrtf(gbn1[3 * I2_ + m] + EPS_);
            gW1Ac[t] = gw1[m * (2 * I2_) + gk] * s;
        }
        if (t < I2_) {
            float s = gbn1[t] * rsqrtf(gbn1[3 * I2_ + t] + EPS_);
            gb1f[t] = s * (gb1[t] - gbn1[2 * I2_ + t]) + gbn1[I2_ + t];
        }
    } break;
    case 5: {
        if (t < I3_ * I2_) {
            int m = t / I2_;
            float s = gbn2[m] * rsqrtf(gbn2[3 * I3_ + m] + EPS_);
            gW2f[t] = gw2[t] * s;
        }
        if (t < I3_) {
            float s = gbn2[t] * rsqrtf(gbn2[3 * I3_ + t] + EPS_);
            gb2f[t] = s * (gb2[t] - gbn2[2 * I3_ + t]) + gbn2[I3_ + t];
        }
    } break;
    case 6: {
        if (t < I1_ * 128) {
            int o = t / 128, k = t % 128;
            float s = fbn1[o] * rsqrtf(fbn1[3 * I1_ + o] + EPS_);
            float acc = 0.f;
            for (int c = 0; c < I1_; c++)
                acc += fw1[o * (2 * I1_) + I1_ + c] * a2_w[c * 128 + k];
            C1[t] = acc * s;
        }
        if (t < I1_) {
            float s = fbn1[t] * rsqrtf(fbn1[3 * I1_ + t] + EPS_);
            float acc = 0.f;
            for (int c = 0; c < I1_; c++)
                acc += fw1[t * (2 * I1_) + I1_ + c] * a2_b[c];
            d1[t] = acc * s;
        }
    } break;
    case 7: {
        if (t < I2_ * 3) {
            int o = t / 3, k = t % 3;
            float s = gbn1[o] * rsqrtf(gbn1[3 * I2_ + o] + EPS_);
            float acc = 0.f;
            for (int c = 0; c < I2_; c++)
                acc += gw1[o * (2 * I2_) + I2_ + c] * a1_w[c * 3 + k];
            C0[t] = acc * s;
        }
        if (t >= I2_ * 3 && t < I2_ * 4) {
            int o = t - I2_ * 3;
            float s = gbn1[o] * rsqrtf(gbn1[3 * I2_ + o] + EPS_);
            float acc = 0.f;
            for (int c = 0; c < I2_; c++)
                acc += gw1[o * (2 * I2_) + I2_ + c] * a1_b[c];
            d0[o] = acc * s;
        }
    } break;
    }
}

// ---------------------------------------------------------------------------
// GEMM body (256 threads). TOUT: write Y transposed n-major with bias folded.
// ---------------------------------------------------------------------------
template <int BM, int BN, int BK, int TM, int TN, bool TOUT>
__device__ __forceinline__
void gemm_body(float* sm,
               const float* __restrict__ W, int ldw,
               const float* __restrict__ X,
               float* __restrict__ Y,
               const float* __restrict__ biasA,
               const float* __restrict__ biasB,
               int M, int N, int K, int bx, int by, int b, int Mfull) {
    const int TX = BN / TN;
    float* Ws = sm;
    float* Xs = sm + BK * BM;
    const int m0 = by * BM;
    const int n0 = bx * BN;
    const float* Xb = X + (size_t)b * K * N;

    const int tid = threadIdx.x;
    const int tx = tid % TX, ty = tid / TX;
    const int tm = ty * TM, tn = tx * TN;

    float acc[TM][TN];
#pragma unroll
    for (int i = 0; i < TM; i++)
#pragma unroll
        for (int j = 0; j < TN; j++) acc[i][j] = 0.f;

    for (int k0 = 0; k0 < K; k0 += BK) {
#pragma unroll
        for (int i = tid; i < BM * BK; i += 256) {
            int m = i / BK, k = i % BK;
            int gm = m0 + m, gk = k0 + k;
            Ws[k * BM + m] = (gm < M) ? W[(size_t)gm * ldw + gk] : 0.f;
        }
#pragma unroll
        for (int i = tid; i < BK * BN; i += 256) {
            int k = i / BN, n = i % BN;
            Xs[k * BN + n] = Xb[(size_t)(k0 + k) * N + n0 + n];
        }
        __syncthreads();
#pragma unroll
        for (int kk = 0; kk < BK; kk++) {
            float a[TM], xv[TN];
#pragma unroll
            for (int i = 0; i < TM; i++) a[i] = Ws[kk * BM + tm + i];
#pragma unroll
            for (int j = 0; j < TN; j++) xv[j] = Xs[kk * BN + tn + j];
#pragma unroll
            for (int i = 0; i < TM; i++)
#pragma unroll
                for (int j = 0; j < TN; j++) acc[i][j] = fmaf(a[i], xv[j], acc[i][j]);
        }
        __syncthreads();
    }
    if (!TOUT) {
        float* Yb = Y + (size_t)b * M * N;
#pragma unroll
        for (int i = 0; i < TM; i++) {
            int m = m0 + tm + i;
            if (m >= M) break;
#pragma unroll
            for (int j = 0; j < TN; j++)
                Yb[(size_t)m * N + n0 + tn + j] = acc[i][j];
        }
    } else {
#pragma unroll
        for (int i = 0; i < TM; i++) {
            float bv = biasA[m0 + tm + i] + biasB[m0 + tm + i];
#pragma unroll
            for (int j = 0; j < TN; j++)
                sm[(tn + j) * (BM + 1) + tm + i] = acc[i][j] + bv;
        }
        __syncthreads();
        float* Yb = Y + (size_t)b * N * Mfull;
        for (int e = tid; e < BN * BM; e += 256) {
            int n = e / BM, m = e % BM;
            Yb[(size_t)(n0 + n) * Mfull + m0 + m] = sm[n * (BM + 1) + m];
        }
    }
}

// ---------------------------------------------------------------------------
// three_nn body (256 threads)
// ---------------------------------------------------------------------------
__device__ __forceinline__
void three_nn_body(float* sm, int id2,
                   const float* __restrict__ sa0_xyz,
                   const float* __restrict__ sa1_xyz,
                   const float* __restrict__ sa2_xyz,
                   int* __restrict__ idx1, float* __restrict__ wt1,
                   int* __restrict__ idx2, float* __restrict__ wt2) {
    float* kx = sm;
    float* ky = sm + 1024;
    float* kz = sm + 2048;
    float* cd = sm + 3072;
    int*   ci = (int*)(sm + 3840);

    int lvl, bx, b;
    if (id2 < 32) { lvl = 0; bx = id2 & 15; b = id2 >> 4; }
    else          { int id3 = id2 - 32; lvl = 1; bx = id3 & 63; b = id3 >> 6; }
    const int NK = lvl ? 1024 : 256;
    const int Nu = lvl ? N0_ : N1_;
    const int CS = NK / 4;
    const float* unknown = lvl ? sa0_xyz : sa1_xyz;
    const float* known   = lvl ? sa1_xyz : sa2_xyz;
    int*   idx = lvl ? idx2 : idx1;
    float* w   = lvl ? wt2  : wt1;

    const float* kb = known + (size_t)b * NK * 3;
    for (int i = threadIdx.x; i < NK; i += 256) {
        kx[i] = kb[i * 3 + 0];
        ky[i] = kb[i * 3 + 1];
        kz[i] = kb[i * 3 + 2];
    }
    __syncthreads();

    int ul = threadIdx.x & 63;
    int ch = threadIdx.x >> 6;
    int u = bx * 64 + ul;
    const float* up = unknown + ((size_t)b * Nu + u) * 3;
    float ux = up[0], uy = up[1], uz = up[2];

    float d0 = 3.4e38f, d1 = 3.4e38f, d2 = 3.4e38f;
    int i0 = 0, i1 = 0, i2 = 0;
    int base = ch * CS;
#pragma unroll 4
    for (int t = 0; t < CS; t++) {
        int i = base + t;
        float dx = ux - kx[i], dy = uy - ky[i], dz = uz - kz[i];
        float d = fmaf(dx, dx, fmaf(dy, dy, dz * dz));
        if (d < d2) {
            if (d < d0)      { d2 = d1; i2 = i1; d1 = d0; i1 = i0; d0 = d; i0 = i; }
            else if (d < d1) { d2 = d1; i2 = i1; d1 = d;  i1 = i; }
            else             { d2 = d;  i2 = i; }
        }
    }
    cd[(ul * 4 + ch) * 3 + 0] = d0; cd[(ul * 4 + ch) * 3 + 1] = d1; cd[(ul * 4 + ch) * 3 + 2] = d2;
    ci[(ul * 4 + ch) * 3 + 0] = i0; ci[(ul * 4 + ch) * 3 + 1] = i1; ci[(ul * 4 + ch) * 3 + 2] = i2;
    __syncthreads();

    if (threadIdx.x < 64) {
        int uu = bx * 64 + threadIdx.x;
        float m0 = 3.4e38f, m1 = 3.4e38f, m2 = 3.4e38f;
        int j0 = 0, j1 = 0, j2 = 0;
#pragma unroll
        for (int c = 0; c < 4; c++) {
#pragma unroll
            for (int t = 0; t < 3; t++) {
                float d = cd[(threadIdx.x * 4 + c) * 3 + t];
                int i = ci[(threadIdx.x * 4 + c) * 3 + t];
                if (d < m2) {
                    if (d < m0)      { m2 = m1; j2 = j1; m1 = m0; j1 = j0; m0 = d; j0 = i; }
                    else if (d < m1) { m2 = m1; j2 = j1; m1 = d;  j1 = i; }
                    else             { m2 = d;  j2 = i; }
                }
            }
        }
        float w0 = 1.f / (m0 + 1e-8f);
        float w1 = 1.f / (m1 + 1e-8f);
        float w2 = 1.f / (m2 + 1e-8f);
        float ws = w0 + w1 + w2;
        size_t o = ((size_t)b * Nu + uu) * 3;
        idx[o] = j0; idx[o + 1] = j1; idx[o + 2] = j2;
        w[o] = w0 / ws; w[o + 1] = w1 / ws; w[o + 2] = w2 / ws;
    }
}

// ---------------------------------------------------------------------------
// util kernel: Tx GEMM (40) + s1t GEMM (96, transposed+bias) + three_nn (160)
// ---------------------------------------------------------------------------
__global__ __launch_bounds__(256)
void util_kernel(const float* __restrict__ W1f,
                 const float* __restrict__ x,
                 float* __restrict__ Tx,
                 const float* __restrict__ C1,
                 const float* __restrict__ sa1f,
                 float* __restrict__ s1t,
                 const float* __restrict__ fb1f,
                 const float* __restrict__ d1v,
                 const float* __restrict__ sa0_xyz,
                 const float* __restrict__ sa1_xyz,
                 const float* __restrict__ sa2_xyz,
                 int* __restrict__ idx1, float* __restrict__ wt1,
                 int* __restrict__ idx2, float* __restrict__ wt2) {
    __shared__ float sm[4608];
    int id = blockIdx.x;
    if (id < 40) {
        int bx = id & 3, r = id >> 2, by = r % 5, b = r / 5;
        gemm_body<64, 64, 16, 4, 4, false>(sm, W1f, DIM_, x, Tx, nullptr, nullptr,
                                           DIM_, N2_, CTX_, bx, by, b, 0);
    } else if (id < 136) {
        int id1 = id - 40;
        int bx = id1 & 15, r = id1 >> 4, by = r % 3, b = r / 3;
        gemm_body<48, 64, 16, 3, 4, true>(sm, C1, 128, sa1f, s1t, fb1f, d1v,
                                          I1_, N1_, 128, bx, by, b, I1_);
    } else {
        three_nn_body(sm, id - 136, sa0_xyz, sa1_xyz, sa2_xyz, idx1, wt1, idx2, wt2);
    }
}

// ---------------------------------------------------------------------------
// fusedA (R8 version): 128 threads, micro-tile 9x4, n-tile 32, grid (8,32).
// Smem double-buffered weights + Xs; h1 on the fly.
// ---------------------------------------------------------------------------
__global__ __launch_bounds__(128)
void fusedA_kernel(const float* __restrict__ W2c,    // (37,144,8)
                   const float* __restrict__ b2f,
                   const float* __restrict__ fW1Ac,  // (18,144,8)
                   const float* __restrict__ Tx,     // (2,296,256)
                   const float* __restrict__ maskg,  // (32,8,256)
                   const float* __restrict__ W1f,    // (296,296)
                   const float* __restrict__ b1f,
                   float* __restrict__ T2t) {        // (32,256,144)
    __shared__ float Wp[2][1152];
    __shared__ float Xp[2][256];
    __shared__ float Hs[144 * 36];

    const int bq = blockIdx.y, b = bq >> 4;
    const int n0 = blockIdx.x * 32;
    const int tid = threadIdx.x;
    const int tx = tid & 7, ty = tid >> 3;
    const int tm = ty * 9, tn = tx * 4;

    const int kl0 = tid >> 5,           nl0 = tid & 31;
    const int kl1 = (tid + 128) >> 5,   nl1 = (tid + 128) & 31;
    float mv0[8], mv1[8];
#pragma unroll
    for (int j = 0; j < 8; j++) {
        mv0[j] = __ldg(maskg + ((size_t)bq * 8 + j) * N2_ + n0 + nl0);
        mv1[j] = __ldg(maskg + ((size_t)bq * 8 + j) * N2_ + n0 + nl1);
    }
    const float* Txb = Tx + (size_t)b * DIM_ * N2_ + n0;

    float acc[9][4];
#pragma unroll
    for (int i = 0; i < 9; i++)
#pragma unroll
        for (int j = 0; j < 4; j++) acc[i][j] = 0.f;

    auto h1v = [&](int gk, int nl, const float* mv) -> float {
        const float4* wp = (const float4*)(W1f + (size_t)gk * DIM_ + CTX_);
        float4 wa = __ldg(wp), wb = __ldg(wp + 1);
        float v = __ldg(Txb + (size_t)gk * N2_ + nl) + __ldg(b1f + gk);
        v += wa.x * mv[0] + wa.y * mv[1] + wa.z * mv[2] + wa.w * mv[3]
           + wb.x * mv[4] + wb.y * mv[5] + wb.z * mv[6] + wb.w * mv[7];
        return fmaxf(v, 0.f);
    };

    float4 w4[3];
    float xv0, xv1;
#pragma unroll
    for (int r = 0; r < 3; r++) {
        int e = tid + r * 128;
        if (e < 288) ((float4*)Wp[0])[e] = ((const float4*)W2c)[e];
    }
    Xp[0][tid] = h1v(kl0, nl0, mv0);
    Xp[0][tid + 128] = h1v(kl1, nl1, mv1);

    for (int kc = 0; kc < 37; kc++) {
        __syncthreads();
        const int cur = kc & 1, nxt = cur ^ 1;
        const bool more = (kc + 1 < 37);
        if (more) {
            const float4* wc = (const float4*)(W2c + (size_t)(kc + 1) * 1152);
#pragma unroll
            for (int r = 0; r < 3; r++) {
                int e = tid + r * 128;
                if (e < 288) w4[r] = wc[e];
            }
            xv0 = h1v((kc + 1) * 8 + kl0, nl0, mv0);
            xv1 = h1v((kc + 1) * 8 + kl1, nl1, mv1);
        }
        const float* Ws = Wp[cur];
        const float* Xs = Xp[cur];
#pragma unroll
        for (int g = 0; g < 2; g++) {
            float4 a4[9];
#pragma unroll
            for (int i = 0; i < 9; i++)
                a4[i] = *(const float4*)&Ws[(tm + i) * 8 + g * 4];
            float4 x0 = *(const float4*)&Xs[(g * 4 + 0) * 32 + tn];
            float4 x1 = *(const float4*)&Xs[(g * 4 + 1) * 32 + tn];
            float4 x2 = *(const float4*)&Xs[(g * 4 + 2) * 32 + tn];
            float4 x3 = *(const float4*)&Xs[(g * 4 + 3) * 32 + tn];
#pragma unroll
            for (int i = 0; i < 9; i++) {
                acc[i][0] = fmaf(a4[i].x, x0.x, acc[i][0]);
                acc[i][1] = fmaf(a4[i].x, x0.y, acc[i][1]);
                acc[i][2] = fmaf(a4[i].x, x0.z, acc[i][2]);
                acc[i][3] = fmaf(a4[i].x, x0.w, acc[i][3]);
                acc[i][0] = fmaf(a4[i].y, x1.x, acc[i][0]);
                acc[i][1] = fmaf(a4[i].y, x1.y, acc[i][1]);
                acc[i][2] = fmaf(a4[i].y, x1.z, acc[i][2]);
                acc[i][3] = fmaf(a4[i].y, x1.w, acc[i][3]);
                acc[i][0] = fmaf(a4[i].z, x2.x, acc[i][0]);
                acc[i][1] = fmaf(a4[i].z, x2.y, acc[i][1]);
                acc[i][2] = fmaf(a4[i].z, x2.z, acc[i][2]);
                acc[i][3] = fmaf(a4[i].z, x2.w, acc[i][3]);
                acc[i][0] = fmaf(a4[i].w, x3.x, acc[i][0]);
                acc[i][1] = fmaf(a4[i].w, x3.y, acc[i][1]);
                acc[i][2] = fmaf(a4[i].w, x3.z, acc[i][2]);
                acc[i][3] = fmaf(a4[i].w, x3.w, acc[i][3]);
            }
        }
        if (more) {
#pragma unroll
            for (int r = 0; r < 3; r++) {
                int e = tid + r * 128;
                if (e < 288) ((float4*)Wp[nxt])[e] = w4[r];
            }
            Xp[nxt][tid] = xv0;
            Xp[nxt][tid + 128] = xv1;
        }
    }
#pragma unroll
    for (int i = 0; i < 9; i++) {
        float bv = __ldg(b2f + tm + i);
        float4 hv;
        hv.x = fmaxf(acc[i][0] + bv, 0.f);
        hv.y = fmaxf(acc[i][1] + bv, 0.f);
        hv.z = fmaxf(acc[i][2] + bv, 0.f);
        hv.w = fmaxf(acc[i][3] + bv, 0.f);
        *(float4*)&Hs[(tm + i) * 36 + tn] = hv;
    }
    __syncthreads();

    float acc2[9][4];
#pragma unroll
    for (int i = 0; i < 9; i++)
#pragma unroll
        for (int j = 0; j < 4; j++) acc2[i][j] = 0.f;

#pragma unroll
    for (int r = 0; r < 3; r++) {
        int e = tid + r * 128;
        if (e < 288) ((float4*)Wp[0])[e] = ((const float4*)fW1Ac)[e];
    }
    for (int kc = 0; kc < 18; kc++) {
        __syncthreads();
        const int cur = kc & 1, nxt = cur ^ 1;
        const bool more = (kc + 1 < 18);
        if (more) {
            const float4* wc = (const float4*)(fW1Ac + (size_t)(kc + 1) * 1152);
#pragma unroll
            for (int r = 0; r < 3; r++) {
                int e = tid + r * 128;
                if (e < 288) w4[r] = wc[e];
            }
        }
        const float* Ws = Wp[cur];
        int kb = kc * 8;
#pragma unroll
        for (int g = 0; g < 2; g++) {
            float4 a4[9];
#pragma unroll
            for (int i = 0; i < 9; i++)
                a4[i] = *(const float4*)&Ws[(tm + i) * 8 + g * 4];
            float4 x0 = *(const float4*)&Hs[(kb + g * 4 + 0) * 36 + tn];
            float4 x1 = *(const float4*)&Hs[(kb + g * 4 + 1) * 36 + tn];
            float4 x2 = *(const float4*)&Hs[(kb + g * 4 + 2) * 36 + tn];
            float4 x3 = *(const float4*)&Hs[(kb + g * 4 + 3) * 36 + tn];
#pragma unroll
            for (int i = 0; i < 9; i++) {
                acc2[i][0] = fmaf(a4[i].x, x0.x, acc2[i][0]);
                acc2[i][1] = fmaf(a4[i].x, x0.y, acc2[i][1]);
                acc2[i][2] = fmaf(a4[i].x, x0.z, acc2[i][2]);
                acc2[i][3] = fmaf(a4[i].x, x0.w, acc2[i][3]);
                acc2[i][0] = fmaf(a4[i].y, x1.x, acc2[i][0]);
                acc2[i][1] = fmaf(a4[i].y, x1.y, acc2[i][1]);
                acc2[i][2] = fmaf(a4[i].y, x1.z, acc2[i][2]);
                acc2[i][3] = fmaf(a4[i].y, x1.w, acc2[i][3]);
                acc2[i][0] = fmaf(a4[i].z, x2.x, acc2[i][0]);
                acc2[i][1] = fmaf(a4[i].z, x2.y, acc2[i][1]);
                acc2[i][2] = fmaf(a4[i].z, x2.z, acc2[i][2]);
                acc2[i][3] = fmaf(a4[i].z, x2.w, acc2[i][3]);
                acc2[i][0] = fmaf(a4[i].w, x3.x, acc2[i][0]);
                acc2[i][1] = fmaf(a4[i].w, x3.y, acc2[i][1]);
                acc2[i][2] = fmaf(a4[i].w, x3.z, acc2[i][2]);
                acc2[i][3] = fmaf(a4[i].w, x3.w, acc2[i][3]);
            }
        }
        if (more) {
#pragma unroll
            for (int r = 0; r < 3; r++) {
                int e = tid + r * 128;
                if (e < 288) ((float4*)Wp[nxt])[e] = w4[r];
            }
        }
    }
#pragma unroll
    for (int j = 0; j < 4; j++) {
        size_t base = ((size_t)bq * N2_ + n0 + tn + j) * I1_ + tm;
#pragma unroll
        for (int i = 0; i < 9; i++) T2t[base + i] = acc2[i][j];
    }
}

// ---------------------------------------------------------------------------
// fusedB (R11 version): n-tile 32 -> grid (32, 32) = 1024 blocks, 128 threads.
// Micro-tile 9x2 (TX=16, TY=8). Warp-contiguous gather into float4-level
// XOR-swizzled smem (rows of 32); weights via L1 LDG; 3 barriers.
// ---------------------------------------------------------------------------
__global__ __launch_bounds__(128)
void fusedB_kernel(const float* __restrict__ T2t,    // (32,256,144)
                   const int* __restrict__ idx1,
                   const float* __restrict__ wt1,
                   const float* __restrict__ s1t,    // (2,1024,144) bias folded
                   const float* __restrict__ fW2c,   // (18,72,8)
                   const float* __restrict__ fb2f,
                   const float* __restrict__ gW1Ac,  // (9,72,8)
                   float* __restrict__ T4t) {        // (32,1024,72)
    extern __shared__ float smem[];
    float* H3s = smem;                 // 144 x 32 swizzled

    const int bq = blockIdx.y, b = bq >> 4;
    const int n0 = blockIdx.x * 32;
    const int tid = threadIdx.x;
    const int warp = tid >> 5, lane = tid & 31;

#pragma unroll 2
    for (int t = 0; t < 8; t++) {
        int nu = warp * 8 + t;
        size_t o = ((size_t)b * N1_ + n0 + nu) * 3;
        int j0 = __ldg(idx1 + o), j1 = __ldg(idx1 + o + 1), j2 = __ldg(idx1 + o + 2);
        float w0 = __ldg(wt1 + o), w1 = __ldg(wt1 + o + 1), w2 = __ldg(wt1 + o + 2);
        const float4* p0 = (const float4*)(T2t + ((size_t)bq * N2_ + j0) * I1_);
        const float4* p1 = (const float4*)(T2t + ((size_t)bq * N2_ + j1) * I1_);
        const float4* p2 = (const float4*)(T2t + ((size_t)bq * N2_ + j2) * I1_);
        const float4* ps = (const float4*)(s1t + ((size_t)b * N1_ + n0 + nu) * I1_);
        {
            float4 a0 = __ldg(p0 + lane), a1 = __ldg(p1 + lane),
                   a2 = __ldg(p2 + lane), s  = __ldg(ps + lane);
            int c = lane * 4;
            int off = c * 32 + ((((nu >> 2) ^ (lane & 7)) << 2) | (nu & 3));
            H3s[off + 0 * 32] = fmaxf(w0 * a0.x + w1 * a1.x + w2 * a2.x + s.x, 0.f);
            H3s[off + 1 * 32] = fmaxf(w0 * a0.y + w1 * a1.y + w2 * a2.y + s.y, 0.f);
            H3s[off + 2 * 32] = fmaxf(w0 * a0.z + w1 * a1.z + w2 * a2.z + s.z, 0.f);
            H3s[off + 3 * 32] = fmaxf(w0 * a0.w + w1 * a1.w + w2 * a2.w + s.w, 0.f);
        }
        if (lane < 4) {
            float4 a0 = __ldg(p0 + 32 + lane), a1 = __ldg(p1 + 32 + lane),
                   a2 = __ldg(p2 + 32 + lane), s  = __ldg(ps + 32 + lane);
            int c = 128 + lane * 4;
            int off = c * 32 + ((((nu >> 2) ^ lane) << 2) | (nu & 3));
            H3s[off + 0 * 32] = fmaxf(w0 * a0.x + w1 * a1.x + w2 * a2.x + s.x, 0.f);
            H3s[off + 1 * 32] = fmaxf(w0 * a0.y + w1 * a1.y + w2 * a2.y + s.y, 0.f);
            H3s[off + 2 * 32] = fmaxf(w0 * a0.z + w1 * a1.z + w2 * a2.z + s.z, 0.f);
            H3s[off + 3 * 32] = fmaxf(w0 * a0.w + w1 * a1.w + w2 * a2.w + s.w, 0.f);
        }
    }
    __syncthreads();

    const int tx = tid & 15, ty = tid >> 4;
    const int tm = ty * 9, tn = tx * 2;
    const int hslot = tx >> 1;
    const int hsub = (tx & 1) << 1;

    float acc[9][2];
#pragma unroll
    for (int i = 0; i < 9; i++) { acc[i][0] = 0.f; acc[i][1] = 0.f; }

    for (int kc = 0; kc < 18; kc++) {
        const float4* wg = (const float4*)(fW2c + (size_t)kc * 576);
        int kb = kc * 8;
#pragma unroll
        for (int g = 0; g < 2; g++) {
            int xsl = (2 * kc + g) & 7;
            int xof = (((hslot ^ xsl) << 2) | hsub);
            float4 a4[9];
#pragma unroll
            for (int i = 0; i < 9; i++)
                a4[i] = __ldg(wg + (tm + i) * 2 + g);
            float2 x0 = *(const float2*)&H3s[(kb + g * 4 + 0) * 32 + xof];
            float2 x1 = *(const float2*)&H3s[(kb + g * 4 + 1) * 32 + xof];
            float2 x2 = *(const float2*)&H3s[(kb + g * 4 + 2) * 32 + xof];
            float2 x3 = *(const float2*)&H3s[(kb + g * 4 + 3) * 32 + xof];
#pragma unroll
            for (int i = 0; i < 9; i++) {
                acc[i][0] = fmaf(a4[i].x, x0.x, acc[i][0]);
                acc[i][1] = fmaf(a4[i].x, x0.y, acc[i][1]);
                acc[i][0] = fmaf(a4[i].y, x1.x, acc[i][0]);
                acc[i][1] = fmaf(a4[i].y, x1.y, acc[i][1]);
                acc[i][0] = fmaf(a4[i].z, x2.x, acc[i][0]);
                acc[i][1] = fmaf(a4[i].z, x2.y, acc[i][1]);
                acc[i][0] = fmaf(a4[i].w, x3.x, acc[i][0]);
                acc[i][1] = fmaf(a4[i].w, x3.y, acc[i][1]);
            }
        }
    }
    __syncthreads();

#pragma unroll
    for (int i = 0; i < 9; i++) {
        float bv = __ldg(fb2f + tm + i);
        int c = tm + i;
        int off = c * 32 + ((((tn >> 2) ^ ((c >> 2) & 7)) << 2) | (tn & 3));
        float2 hv;
        hv.x = fmaxf(acc[i][0] + bv, 0.f);
        hv.y = fmaxf(acc[i][1] + bv, 0.f);
        *(float2*)&H3s[off] = hv;
    }
    __syncthreads();

    float acc2[9][2];
#pragma unroll
    for (int i = 0; i < 9; i++) { acc2[i][0] = 0.f; acc2[i][1] = 0.f; }

    for (int kc = 0; kc < 9; kc++) {
        const float4* wg = (const float4*)(gW1Ac + (size_t)kc * 576);
        int kb = kc * 8;
#pragma unroll
        for (int g = 0; g < 2; g++) {
            int xsl = (2 * kc + g) & 7;
            int xof = (((hslot ^ xsl) << 2) | hsub);
            float4 a4[9];
#pragma unroll
            for (int i = 0; i < 9; i++)
                a4[i] = __ldg(wg + (tm + i) * 2 + g);
            float2 x0 = *(const float2*)&H3s[(kb + g * 4 + 0) * 32 + xof];
            float2 x1 = *(const float2*)&H3s[(kb + g * 4 + 1) * 32 + xof];
            float2 x2 = *(const float2*)&H3s[(kb + g * 4 + 2) * 32 + xof];
            float2 x3 = *(const float2*)&H3s[(kb + g * 4 + 3) * 32 + xof];
#pragma unroll
            for (int i = 0; i < 9; i++) {
                acc2[i][0] = fmaf(a4[i].x, x0.x, acc2[i][0]);
                acc2[i][1] = fmaf(a4[i].x, x0.y, acc2[i][1]);
                acc2[i][0] = fmaf(a4[i].y, x1.x, acc2[i][0]);
                acc2[i][1] = fmaf(a4[i].y, x1.y, acc2[i][1]);
                acc2[i][0] = fmaf(a4[i].z, x2.x, acc2[i][0]);
                acc2[i][1] = fmaf(a4[i].z, x2.y, acc2[i][1]);
                acc2[i][0] = fmaf(a4[i].w, x3.x, acc2[i][0]);
                acc2[i][1] = fmaf(a4[i].w, x3.y, acc2[i][1]);
            }
        }
    }
#pragma unroll
    for (int j = 0; j < 2; j++) {
        size_t base = ((size_t)bq * N1_ + n0 + tn + j) * I2_ + tm;
#pragma unroll
        for (int i = 0; i < 9; i++) T4t[base + i] = acc2[i][j];
    }
}

// ---------------------------------------------------------------------------
// final (R8 version): 256 threads, grid (N0/256, BQ), static smem
// ---------------------------------------------------------------------------
__global__ __launch_bounds__(256)
void final_fuse_kernel(const float* __restrict__ T4t,
                       const int* __restrict__ idx,
                       const float* __restrict__ wt,
                       const float* __restrict__ sa0f,
                       const float* __restrict__ C0,
                       const float* __restrict__ d0v,
                       const float* __restrict__ gb1,
                       const float* __restrict__ gW2,
                       const float* __restrict__ gb2,
                       const float* __restrict__ ow,
                       const float* __restrict__ ob,
                       float* __restrict__ out) {
    __shared__ float gT[I2_ * I3_];
    __shared__ float c0s[I2_ * 3];
    __shared__ float bs[I2_];
    __shared__ float gbs[I3_], ows[I3_];
    int tid = threadIdx.x;
    for (int e = tid; e < I2_ * I3_; e += 256) {
        int c = e / I3_, m = e % I3_;
        gT[e] = gW2[m * I2_ + c];
    }
    if (tid < I2_ * 3) c0s[tid] = C0[tid];
    if (tid < I2_) bs[tid] = d0v[tid] + gb1[tid];
    if (tid < I3_) { gbs[tid] = gb2[tid]; ows[tid] = ow[tid]; }
    __syncthreads();

    int bq = blockIdx.y, b = bq >> 4;
    int nu = blockIdx.x * 256 + tid;
    size_t o = ((size_t)b * N0_ + nu) * 3;
    int j0 = idx[o], j1 = idx[o + 1], j2 = idx[o + 2];
    float w0 = wt[o], w1 = wt[o + 1], w2 = wt[o + 2];
    const float4* p0 = (const float4*)(T4t + ((size_t)bq * N1_ + j0) * I2_);
    const float4* p1 = (const float4*)(T4t + ((size_t)bq * N1_ + j1) * I2_);
    const float4* p2 = (const float4*)(T4t + ((size_t)bq * N1_ + j2) * I2_);
    float f0 = sa0f[((size_t)b * 3 + 0) * N0_ + nu];
    float f1 = sa0f[((size_t)b * 3 + 1) * N0_ + nu];
    float f2 = sa0f[((size_t)b * 3 + 2) * N0_ + nu];

    float acc[I3_];
#pragma unroll
    for (int m = 0; m < I3_; m++) acc[m] = 0.f;

#pragma unroll 3
    for (int cc = 0; cc < 18; cc++) {
        float4 a0 = p0[cc], a1 = p1[cc], a2 = p2[cc];
        int c = cc * 4;
        float hv[4];
        hv[0] = fmaxf(w0 * a0.x + w1 * a1.x + w2 * a2.x + c0s[(c + 0) * 3] * f0 + c0s[(c + 0) * 3 + 1] * f1 + c0s[(c + 0) * 3 + 2] * f2 + bs[c + 0], 0.f);
        hv[1] = fmaxf(w0 * a0.y + w1 * a1.y + w2 * a2.y + c0s[(c + 1) * 3] * f0 + c0s[(c + 1) * 3 + 1] * f1 + c0s[(c + 1) * 3 + 2] * f2 + bs[c + 1], 0.f);
        hv[2] = fmaxf(w0 * a0.z + w1 * a1.z + w2 * a2.z + c0s[(c + 2) * 3] * f0 + c0s[(c + 2) * 3 + 1] * f1 + c0s[(c + 2) * 3 + 2] * f2 + bs[c + 2], 0.f);
        hv[3] = fmaxf(w0 * a0.w + w1 * a1.w + w2 * a2.w + c0s[(c + 3) * 3] * f0 + c0s[(c + 3) * 3 + 1] * f1 + c0s[(c + 3) * 3 + 2] * f2 + bs[c + 3], 0.f);
#pragma unroll
        for (int q = 0; q < 4; q++) {
            const float4* g4 = (const float4*)&gT[(c + q) * I3_];
#pragma unroll
            for (int mm = 0; mm < 9; mm++) {
                float4 g = g4[mm];
                acc[mm * 4 + 0] = fmaf(g.x, hv[q], acc[mm * 4 + 0]);
                acc[mm * 4 + 1] = fmaf(g.y, hv[q], acc[mm * 4 + 1]);
                acc[mm * 4 + 2] = fmaf(g.z, hv[q], acc[mm * 4 + 2]);
                acc[mm * 4 + 3] = fmaf(g.w, hv[q], acc[mm * 4 + 3]);
            }
        }
    }
    float r = ob[0];
#pragma unroll
    for (int m = 0; m < I3_; m++) r = fmaf(ows[m], fmaxf(acc[m] + gbs[m], 0.f), r);
    out[(size_t)bq * N0_ + nu] = r;
}

// ---------------------------------------------------------------------------
// Launch
// ---------------------------------------------------------------------------
static inline int cdiv(int a, int b) { return (a + b - 1) / b; }

extern "C" void kernel_launch(void* const* d_in, const int* in_sizes, int n_in,
                              void* d_out, int out_size) {
    const float* x        = (const float*)d_in[0];
    const float* mask     = (const float*)d_in[1];
    const float* sa0_feat = (const float*)d_in[2];
    const float* sa1_feat = (const float*)d_in[3];
    const float* sa0_xyz  = (const float*)d_in[4];
    const float* sa1_xyz  = (const float*)d_in[5];
    const float* sa2_xyz  = (const float*)d_in[6];
    const float* w1       = (const float*)d_in[7];
    const float* b1       = (const float*)d_in[8];
    const float* bn1      = (const float*)d_in[9];
    const float* w2       = (const float*)d_in[10];
    const float* b2       = (const float*)d_in[11];
    const float* bn2      = (const float*)d_in[12];
    const float* a1_w     = (const float*)d_in[13];
    const float* a1_b     = (const float*)d_in[14];
    const float* a2_w     = (const float*)d_in[15];
    const float* a2_b     = (const float*)d_in[16];
    const float* fp1_w1   = (const float*)d_in[17];
    const float* fp1_b1   = (const float*)d_in[18];
    const float* fp1_bn1  = (const float*)d_in[19];
    const float* fp1_w2   = (const float*)d_in[20];
    const float* fp1_b2   = (const float*)d_in[21];
    const float* fp1_bn2  = (const float*)d_in[22];
    const float* fp2_w1   = (const float*)d_in[23];
    const float* fp2_b1   = (const float*)d_in[24];
    const float* fp2_bn1  = (const float*)d_in[25];
    const float* fp2_w2   = (const float*)d_in[26];
    const float* fp2_b2   = (const float*)d_in[27];
    const float* fp2_bn2  = (const float*)d_in[28];
    const float* out_w    = (const float*)d_in[29];
    const float* out_b    = (const float*)d_in[30];
    float* out = (float*)d_out;

    float *W1f, *b1f, *W2c, *b2f, *fW1Ac, *fb1f, *fW2c, *fb2f, *gW1Ac, *gb1f, *gW2f, *gb2f;
    float *C1, *d1, *C0, *d0;
    float *Tx, *T2t, *s1t, *T4t;
    int *idx1, *idx2;
    float *wt1, *wt2;
    cudaGetSymbolAddress((void**)&W1f, g_W1f);     cudaGetSymbolAddress((void**)&b1f, g_b1f);
    cudaGetSymbolAddress((void**)&W2c, g_W2c);     cudaGetSymbolAddress((void**)&b2f, g_b2f);
    cudaGetSymbolAddress((void**)&fW1Ac, g_fW1Ac); cudaGetSymbolAddress((void**)&fb1f, g_fb1f);
    cudaGetSymbolAddress((void**)&fW2c, g_fW2c);   cudaGetSymbolAddress((void**)&fb2f, g_fb2f);
    cudaGetSymbolAddress((void**)&gW1Ac, g_gW1Ac); cudaGetSymbolAddress((void**)&gb1f, g_gb1f);
    cudaGetSymbolAddress((void**)&gW2f, g_gW2f);   cudaGetSymbolAddress((void**)&gb2f, g_gb2f);
    cudaGetSymbolAddress((void**)&C1, g_C1);       cudaGetSymbolAddress((void**)&d1, g_d1);
    cudaGetSymbolAddress((void**)&C0, g_C0);       cudaGetSymbolAddress((void**)&d0, g_d0);
    cudaGetSymbolAddress((void**)&Tx, g_Tx);
    cudaGetSymbolAddress((void**)&T2t, g_T2t);
    cudaGetSymbolAddress((void**)&s1t, g_s1t);
    cudaGetSymbolAddress((void**)&T4t, g_T4t);
    cudaGetSymbolAddress((void**)&idx1, g_idx1);   cudaGetSymbolAddress((void**)&wt1, g_wt1);
    cudaGetSymbolAddress((void**)&idx2, g_idx2);   cudaGetSymbolAddress((void**)&wt2, g_wt2);

    // 1) weight prep
    prep_kernel<<<738, 256>>>(w1, b1, bn1, w2, b2, bn2,
                              fp1_w1, fp1_b1, fp1_bn1, fp1_w2, fp1_b2, fp1_bn2,
                              fp2_w1, fp2_b1, fp2_bn1, fp2_w2, fp2_b2, fp2_bn2,
                              a1_w, a1_b, a2_w, a2_b,
                              W1f, b1f, W2c, b2f, fW1Ac, fb1f, fW2c, fb2f,
                              gW1Ac, gb1f, gW2f, gb2f, C1, d1, C0, d0);
    // 2) util: Tx GEMM + s1t GEMM (transposed, bias folded) + three_nn
    util_kernel<<<296, 256>>>(W1f, x, Tx, C1, sa1_feat, s1t, fb1f, d1,
                              sa0_xyz, sa1_xyz, sa2_xyz,
                              idx1, wt1, idx2, wt2);
    // 3) fusedA (R8 config: smem dbuf weights, 9x4, n-tile 32)
    {
        dim3 grid(N2_ / 32, BQ_);
        fusedA_kernel<<<grid, 128>>>(W2c, b2f, fW1Ac, Tx, mask, W1f, b1f, T2t);
    }
    // 4) fusedB (R11 config: n-tile 32, grid 1024)
    {
        const int smem_bytes = (144 * 32) * 4;
        cudaFuncSetAttribute(fusedB_kernel,
                             cudaFuncAttributeMaxDynamicSharedMemorySize, smem_bytes);
        dim3 grid(N1_ / 32, BQ_);
        fusedB_kernel<<<grid, 128, smem_bytes>>>(T2t, idx1, wt1, s1t,
                                                 fW2c, fb2f, gW1Ac, T4t);
    }
    // 5) final (R8 config: 256 threads)
    {
        dim3 grid(N0_ / 256, BQ_);
        final_fuse_kernel<<<grid, 256>>>(T4t, idx2, wt2, sa0_feat, C0, d0, gb1f,
                                         gW2f, gb2f, out_w, out_b, out);
    }
}